// round 12
// baseline (speedup 1.0000x reference)
#include <cuda_runtime.h>

// MomentumLIF: x[N,T,D] f32 -> spikes[N,T,D] f32
//   v_t = mom*v + x_t - lamb*u
//   u_t = 0.5*u + v_t        (decay = 1 - 1/tau, tau=2)
//   s_t = (u_t >= 1);  u_t = 0 if spiked (hard reset)
// One thread = 4 consecutive d (float4), serial over T=64 with u/v in regs.
// R11: R8 config (proven best: bench 46.5us, cold 37.9us, DRAM 72.9%) with
// prefetch depth 6 -> 8. Measured-closed levers: cache hints (R2/R7/R9 all
// lost to plain policy), occupancy via float2 (R10: DRAM fell), block=128
// (R3: neutral-worse). Cold floor for 256MB mixed R/W is ~36-37.5us; this
// is a last micro-step toward it via deeper per-warp read-ahead.

#define LIF_N 64
#define LIF_T 64
#define LIF_D 8192
#define LIF_D4 (LIF_D / 4)          // 2048 float4 per row
#define THREADS 256
#define PF 8                        // prefetch depth

__global__ __launch_bounds__(THREADS)
void momentum_lif_kernel(const float4* __restrict__ x,
                         const float* __restrict__ p_mom,
                         const float* __restrict__ p_lamb,
                         float4* __restrict__ out) {
    const float mom = __ldg(p_mom);
    const float lb  = __ldg(p_lamb);

    int idx = blockIdx.x * THREADS + threadIdx.x;   // 0 .. N*D4-1 (exact grid)
    int n  = idx >> 11;          // idx / 2048
    int d4 = idx & 2047;         // idx % 2048

    const float4* xp = x   + (size_t)n * LIF_T * LIF_D4 + d4;
    float4*       op = out + (size_t)n * LIF_T * LIF_D4 + d4;

    float ux = 0.f, uy = 0.f, uz = 0.f, uw = 0.f;
    float vx = 0.f, vy = 0.f, vz = 0.f, vw = 0.f;

    // Prime the pipeline: PF independent loads in flight before any compute.
    float4 buf[PF];
#pragma unroll
    for (int i = 0; i < PF; ++i)
        buf[i] = xp[(size_t)i * LIF_D4];

#pragma unroll
    for (int t = 0; t < LIF_T; ++t) {
        float4 xv = buf[t % PF];
        // Refill the slot before the dependent math so the load overlaps
        // this iteration's compute + store.
        if (t + PF < LIF_T)
            buf[t % PF] = xp[(size_t)(t + PF) * LIF_D4];

        // lane x
        vx = fmaf(mom, vx, xv.x);
        vx = fmaf(-lb, ux, vx);
        ux = fmaf(0.5f, ux, vx);
        float sx = (ux >= 1.0f) ? 1.0f : 0.0f;
        ux = (ux >= 1.0f) ? 0.0f : ux;
        // lane y
        vy = fmaf(mom, vy, xv.y);
        vy = fmaf(-lb, uy, vy);
        uy = fmaf(0.5f, uy, vy);
        float sy = (uy >= 1.0f) ? 1.0f : 0.0f;
        uy = (uy >= 1.0f) ? 0.0f : uy;
        // lane z
        vz = fmaf(mom, vz, xv.z);
        vz = fmaf(-lb, uz, vz);
        uz = fmaf(0.5f, uz, vz);
        float sz = (uz >= 1.0f) ? 1.0f : 0.0f;
        uz = (uz >= 1.0f) ? 0.0f : uz;
        // lane w
        vw = fmaf(mom, vw, xv.w);
        vw = fmaf(-lb, uw, vw);
        uw = fmaf(0.5f, uw, vw);
        float sw = (uw >= 1.0f) ? 1.0f : 0.0f;
        uw = (uw >= 1.0f) ? 0.0f : uw;

        op[(size_t)t * LIF_D4] = make_float4(sx, sy, sz, sw);   // plain store
    }
}

extern "C" void kernel_launch(void* const* d_in, const int* in_sizes, int n_in,
                              void* d_out, int out_size) {
    const float4* x      = (const float4*)d_in[0];
    const float*  p_mom  = (const float*)d_in[1];
    const float*  p_lamb = (const float*)d_in[2];
    float4*       out    = (float4*)d_out;

    const int total = LIF_N * LIF_D4;           // 131072 threads
    momentum_lif_kernel<<<total / THREADS, THREADS>>>(x, p_mom, p_lamb, out);
}

// round 14
// speedup vs baseline: 1.0652x; 1.0652x over previous
#include <cuda_runtime.h>

// MomentumLIF: x[N,T,D] f32 -> spikes[N,T,D] f32
//   v_t = mom*v + x_t - lamb*u
//   u_t = 0.5*u + v_t        (decay = 1 - 1/tau, tau=2)
//   s_t = (u_t >= 1);  u_t = 0 if spiked (hard reset)
// One thread = 4 consecutive d (float4), serial over T=64 with u/v in regs.
//
// FINAL (= R8, the measured-best config: bench 46.5us, cold 37.9us,
// DRAM 72.9% vs a ~36-37.5us mixed R/W floor for 256MB of traffic).
// Search summary — all alternatives measured and rejected:
//   - .cs / evict_last(1.0) / evict_last(0.5) cache hints: all slower than
//     plain policy (graph replays reuse L2 under default replacement;
//     hints either force writeback or thrash the cyclic scan).
//   - float2 decomposition (2x occupancy): DRAM% fell — latency hiding
//     was already sufficient at 888 thr/SM.
//   - 128-thread blocks: neutral-to-worse.
//   - PF=8: collapsed by ptxas, neutral.

#define LIF_N 64
#define LIF_T 64
#define LIF_D 8192
#define LIF_D4 (LIF_D / 4)          // 2048 float4 per row
#define THREADS 256
#define PF 6                        // prefetch depth

__global__ __launch_bounds__(THREADS)
void momentum_lif_kernel(const float4* __restrict__ x,
                         const float* __restrict__ p_mom,
                         const float* __restrict__ p_lamb,
                         float4* __restrict__ out) {
    const float mom = __ldg(p_mom);
    const float lb  = __ldg(p_lamb);

    int idx = blockIdx.x * THREADS + threadIdx.x;   // 0 .. N*D4-1 (exact grid)
    int n  = idx >> 11;          // idx / 2048
    int d4 = idx & 2047;         // idx % 2048

    const float4* xp = x   + (size_t)n * LIF_T * LIF_D4 + d4;
    float4*       op = out + (size_t)n * LIF_T * LIF_D4 + d4;

    float ux = 0.f, uy = 0.f, uz = 0.f, uw = 0.f;
    float vx = 0.f, vy = 0.f, vz = 0.f, vw = 0.f;

    // Prime the pipeline: PF independent loads in flight before any compute.
    float4 buf[PF];
#pragma unroll
    for (int i = 0; i < PF; ++i)
        buf[i] = xp[(size_t)i * LIF_D4];

#pragma unroll
    for (int t = 0; t < LIF_T; ++t) {
        float4 xv = buf[t % PF];
        // Refill the slot before the dependent math so the load overlaps
        // this iteration's compute + store.
        if (t + PF < LIF_T)
            buf[t % PF] = xp[(size_t)(t + PF) * LIF_D4];

        // lane x
        vx = fmaf(mom, vx, xv.x);
        vx = fmaf(-lb, ux, vx);
        ux = fmaf(0.5f, ux, vx);
        float sx = (ux >= 1.0f) ? 1.0f : 0.0f;
        ux = (ux >= 1.0f) ? 0.0f : ux;
        // lane y
        vy = fmaf(mom, vy, xv.y);
        vy = fmaf(-lb, uy, vy);
        uy = fmaf(0.5f, uy, vy);
        float sy = (uy >= 1.0f) ? 1.0f : 0.0f;
        uy = (uy >= 1.0f) ? 0.0f : uy;
        // lane z
        vz = fmaf(mom, vz, xv.z);
        vz = fmaf(-lb, uz, vz);
        uz = fmaf(0.5f, uz, vz);
        float sz = (uz >= 1.0f) ? 1.0f : 0.0f;
        uz = (uz >= 1.0f) ? 0.0f : uz;
        // lane w
        vw = fmaf(mom, vw, xv.w);
        vw = fmaf(-lb, uw, vw);
        uw = fmaf(0.5f, uw, vw);
        float sw = (uw >= 1.0f) ? 1.0f : 0.0f;
        uw = (uw >= 1.0f) ? 0.0f : uw;

        op[(size_t)t * LIF_D4] = make_float4(sx, sy, sz, sw);   // plain store
    }
}

extern "C" void kernel_launch(void* const* d_in, const int* in_sizes, int n_in,
                              void* d_out, int out_size) {
    const float4* x      = (const float4*)d_in[0];
    const float*  p_mom  = (const float*)d_in[1];
    const float*  p_lamb = (const float*)d_in[2];
    float4*       out    = (float4*)d_out;

    const int total = LIF_N * LIF_D4;           // 131072 threads
    momentum_lif_kernel<<<total / THREADS, THREADS>>>(x, p_mom, p_lamb, out);
}